// round 1
// baseline (speedup 1.0000x reference)
#include <cuda_runtime.h>

// Problem constants
// features: [32, 768, 32, 32]  -> F[b, c, hw], hw = 1024
// query:    [32, 16, 32, 32]   -> Q[b, q, hw]
// W:        [64, 16, 768]      -> A[r, c] with r = k*16 + q  (1024 x 768)
//
// Per batch b: Cmat = A @ F_b  (1024 x 1024), dist2[b,k] = sum_{q,hw} (Cmat - Q)^2
// codes[b] = argmin_k dist2 ; sel = recompute 16 rows of the GEMM for k = codes[b]
// commit_loss = sum_b min_k dist2[b,k] / 524288

__device__ float g_dist2[32 * 64];
__device__ int   g_codes[32];

__global__ void zero_dist_kernel() {
    g_dist2[blockIdx.x * blockDim.x + threadIdx.x] = 0.0f;
}

// 128x128x16 fp32 GEMM tile with fused squared-difference reduction epilogue.
// grid = (8 hw-tiles, 8 row-tiles, 32 batches), 256 threads, 8x8 per thread.
__global__ __launch_bounds__(256, 2)
void dist_gemm_kernel(const float* __restrict__ F,
                      const float* __restrict__ Q,
                      const float* __restrict__ W)
{
    const int b       = blockIdx.z;
    const int rowBase = blockIdx.y * 128;   // row r = k*16+q
    const int colBase = blockIdx.x * 128;   // hw

    const float* Ag = W;                               // [1024, 768]
    const float* Bg = F + (size_t)b * 768 * 1024;      // [768, 1024]

    __shared__ float As[2][16][128];   // transposed: As[c][row]
    __shared__ float Bs[2][16][128];   // Bs[c][hw]
    __shared__ float sdist[8];

    const int t  = threadIdx.x;
    const int tx = t & 15;
    const int ty = t >> 4;

    // load-index decomposition
    const int c4   = t & 3;          // which float4 within the 16-wide k slab (A)
    const int row0 = t >> 2;         // A rows: row0 and row0+64
    const int hw4  = t & 31;         // B float4 column
    const int cb0  = t >> 5;         // B c rows: cb0 and cb0+8

    float acc[8][8];
    #pragma unroll
    for (int i = 0; i < 8; ++i)
        #pragma unroll
        for (int j = 0; j < 8; ++j) acc[i][j] = 0.0f;

    // ---- preload k-tile 0 directly into smem buffer 0 ----
    {
        const float* pa = Ag + (size_t)(rowBase + row0) * 768 + c4 * 4;
        float4 v = *(const float4*)pa;
        As[0][c4 * 4 + 0][row0] = v.x;
        As[0][c4 * 4 + 1][row0] = v.y;
        As[0][c4 * 4 + 2][row0] = v.z;
        As[0][c4 * 4 + 3][row0] = v.w;
        v = *(const float4*)(pa + 64 * 768);
        As[0][c4 * 4 + 0][row0 + 64] = v.x;
        As[0][c4 * 4 + 1][row0 + 64] = v.y;
        As[0][c4 * 4 + 2][row0 + 64] = v.z;
        As[0][c4 * 4 + 3][row0 + 64] = v.w;

        const float* pb = Bg + (size_t)cb0 * 1024 + colBase + hw4 * 4;
        *(float4*)&Bs[0][cb0][hw4 * 4]     = *(const float4*)pb;
        *(float4*)&Bs[0][cb0 + 8][hw4 * 4] = *(const float4*)(pb + 8 * 1024);
    }
    __syncthreads();

    int buf = 0;
    for (int kt = 0; kt < 48; ++kt) {
        float4 a0, a1, b0, b1;
        if (kt < 47) {
            const int kb = (kt + 1) * 16;
            const float* pa = Ag + (size_t)(rowBase + row0) * 768 + kb + c4 * 4;
            a0 = *(const float4*)pa;
            a1 = *(const float4*)(pa + 64 * 768);
            const float* pb = Bg + (size_t)(kb + cb0) * 1024 + colBase + hw4 * 4;
            b0 = *(const float4*)pb;
            b1 = *(const float4*)(pb + 8 * 1024);
        }

        #pragma unroll
        for (int kk = 0; kk < 16; ++kk) {
            float ar[8], br[8];
            *(float4*)&ar[0] = *(const float4*)&As[buf][kk][ty * 8];
            *(float4*)&ar[4] = *(const float4*)&As[buf][kk][ty * 8 + 4];
            *(float4*)&br[0] = *(const float4*)&Bs[buf][kk][tx * 8];
            *(float4*)&br[4] = *(const float4*)&Bs[buf][kk][tx * 8 + 4];
            #pragma unroll
            for (int i = 0; i < 8; ++i)
                #pragma unroll
                for (int j = 0; j < 8; ++j)
                    acc[i][j] += ar[i] * br[j];
        }

        if (kt < 47) {
            const int nb = buf ^ 1;
            As[nb][c4 * 4 + 0][row0] = a0.x;
            As[nb][c4 * 4 + 1][row0] = a0.y;
            As[nb][c4 * 4 + 2][row0] = a0.z;
            As[nb][c4 * 4 + 3][row0] = a0.w;
            As[nb][c4 * 4 + 0][row0 + 64] = a1.x;
            As[nb][c4 * 4 + 1][row0 + 64] = a1.y;
            As[nb][c4 * 4 + 2][row0 + 64] = a1.z;
            As[nb][c4 * 4 + 3][row0 + 64] = a1.w;
            *(float4*)&Bs[nb][cb0][hw4 * 4]     = b0;
            *(float4*)&Bs[nb][cb0 + 8][hw4 * 4] = b1;
            __syncthreads();
            buf = nb;
        }
    }

    // ---- fused epilogue: sum of squared differences vs query ----
    if (t < 8) sdist[t] = 0.0f;
    __syncthreads();

    const float* Qb = Q + (size_t)b * 16 * 1024;
    float rs = 0.0f;
    #pragma unroll
    for (int i = 0; i < 8; ++i) {
        const int grow = rowBase + ty * 8 + i;
        const int qrow = grow & 15;
        const float* qp = Qb + (size_t)qrow * 1024 + colBase + tx * 8;
        #pragma unroll
        for (int j = 0; j < 8; ++j) {
            float d = acc[i][j] - qp[j];
            rs += d * d;
        }
    }
    // each thread's 8 rows fall in exactly one 16-row (one k) group: k_local = ty/2
    atomicAdd(&sdist[ty >> 1], rs);
    __syncthreads();

    if (t < 8)
        atomicAdd(&g_dist2[b * 64 + blockIdx.y * 8 + t], sdist[t]);
}

// argmin over K=64 per batch, write codes (as float) and commit_loss.
__global__ void argmin_kernel(float* __restrict__ out)
{
    __shared__ float smin[32];
    const int b = threadIdx.x;   // 32 threads
    float best = 3.4e38f;
    int bi = 0;
    #pragma unroll 8
    for (int k = 0; k < 64; ++k) {
        float v = g_dist2[b * 64 + k];
        if (v < best) { best = v; bi = k; }
    }
    g_codes[b] = bi;
    out[524288 + b] = (float)bi;
    smin[b] = best;
    __syncthreads();
    if (b == 0) {
        float s = 0.0f;
        #pragma unroll
        for (int i = 0; i < 32; ++i) s += smin[i];
        out[524320] = s / 524288.0f;
    }
}

// Recompute sel[b] = W[codes[b]] @ F_b  (16 x 1024 per batch).
// grid = (8 hw-tiles, 32 batches), 128 threads, one hw column per thread.
__global__ __launch_bounds__(128)
void sel_kernel(const float* __restrict__ F,
                const float* __restrict__ W,
                float* __restrict__ out)
{
    __shared__ float Ws[16 * 768];   // 48 KB
    const int b       = blockIdx.y;
    const int colBase = blockIdx.x * 128;
    const int code    = g_codes[b];

    const float* wsrc = W + (size_t)code * 16 * 768;
    for (int i = threadIdx.x; i < 16 * 768; i += 128)
        Ws[i] = wsrc[i];
    __syncthreads();

    const int col = colBase + threadIdx.x;
    const float* f = F + (size_t)b * 768 * 1024 + col;

    float acc[16];
    #pragma unroll
    for (int q = 0; q < 16; ++q) acc[q] = 0.0f;

    for (int c = 0; c < 768; ++c) {
        const float fv = f[(size_t)c * 1024];
        #pragma unroll
        for (int q = 0; q < 16; ++q)
            acc[q] += Ws[q * 768 + c] * fv;
    }

    float* op = out + (size_t)b * 16 * 1024 + col;
    #pragma unroll
    for (int q = 0; q < 16; ++q)
        op[(size_t)q * 1024] = acc[q];
}

extern "C" void kernel_launch(void* const* d_in, const int* in_sizes, int n_in,
                              void* d_out, int out_size)
{
    const float* F = (const float*)d_in[0];   // features [32,768,32,32]
    const float* Q = (const float*)d_in[1];   // query    [32,16,32,32]
    const float* W = (const float*)d_in[2];   // W        [64,16,768]
    float* out = (float*)d_out;

    zero_dist_kernel<<<8, 256>>>();
    dist_gemm_kernel<<<dim3(8, 8, 32), 256>>>(F, Q, W);
    argmin_kernel<<<1, 32>>>(out);
    sel_kernel<<<dim3(8, 32), 128>>>(F, W, out);
}

// round 2
// speedup vs baseline: 1.1640x; 1.1640x over previous
#include <cuda_runtime.h>

// features: [32, 768, 32, 32]  -> F[b, c, hw], hw = 1024
// query:    [32, 16, 32, 32]   -> Q[b, q, hw]
// W:        [64, 16, 768]      -> A[r, c] with r = k*16 + q  (1024 x 768)
//
// Per batch b: Cmat = A @ F_b  (1024 x 1024), dist2[b,k] = sum_{q,hw} (Cmat - Q)^2
// codes[b] = argmin_k dist2 ; sel = recompute 16 rows of the GEMM for k = codes[b]
// commit_loss = sum_b min_k dist2[b,k] / 524288

__device__ float g_dist2[32 * 64];
__device__ int   g_codes[32];

__global__ void zero_dist_kernel() {
    g_dist2[blockIdx.x * blockDim.x + threadIdx.x] = 0.0f;
}

// ---- packed f32x2 helpers (sm_103a FFMA2 path, PTX-only) ----
__device__ __forceinline__ unsigned long long bcast2(float x) {
    unsigned long long r;
    asm("mov.b64 %0, {%1, %1};" : "=l"(r) : "f"(x));
    return r;
}
__device__ __forceinline__ void ffma2(unsigned long long& d,
                                      unsigned long long a,
                                      unsigned long long b) {
    asm("fma.rn.f32x2 %0, %1, %2, %0;" : "+l"(d) : "l"(a), "l"(b));
}
__device__ __forceinline__ float lo32(unsigned long long v) {
    return __uint_as_float((unsigned)(v & 0xffffffffull));
}
__device__ __forceinline__ float hi32(unsigned long long v) {
    return __uint_as_float((unsigned)(v >> 32));
}

// 128x128x16 fp32 GEMM tile, f32x2-packed accumulators, fused sq-diff epilogue.
// grid = (8 hw-tiles, 8 row-tiles, 32 batches), 256 threads, 8x8 per thread.
__global__ __launch_bounds__(256, 2)
void dist_gemm_kernel(const float* __restrict__ F,
                      const float* __restrict__ Q,
                      const float* __restrict__ W)
{
    const int b       = blockIdx.z;
    const int rowBase = blockIdx.y * 128;   // row r = k*16+q
    const int colBase = blockIdx.x * 128;   // hw

    const float* Ag = W;                               // [1024, 768]
    const float* Bg = F + (size_t)b * 768 * 1024;      // [768, 1024]

    __shared__ float As[2][16][128];   // transposed: As[c][row]
    __shared__ float Bs[2][16][128];   // Bs[c][hw]
    __shared__ float sdist[8];

    const int t  = threadIdx.x;
    const int tx = t & 15;
    const int ty = t >> 4;

    const int c4   = t & 3;
    const int row0 = t >> 2;
    const int hw4  = t & 31;
    const int cb0  = t >> 5;

    // accumulators: acc2[i][jp] = (col jp*2, col jp*2+1) packed f32x2
    unsigned long long acc2[8][4];
    #pragma unroll
    for (int i = 0; i < 8; ++i)
        #pragma unroll
        for (int j = 0; j < 4; ++j) acc2[i][j] = 0ull;

    // ---- preload k-tile 0 ----
    {
        const float* pa = Ag + (size_t)(rowBase + row0) * 768 + c4 * 4;
        float4 v = *(const float4*)pa;
        As[0][c4 * 4 + 0][row0] = v.x;
        As[0][c4 * 4 + 1][row0] = v.y;
        As[0][c4 * 4 + 2][row0] = v.z;
        As[0][c4 * 4 + 3][row0] = v.w;
        v = *(const float4*)(pa + 64 * 768);
        As[0][c4 * 4 + 0][row0 + 64] = v.x;
        As[0][c4 * 4 + 1][row0 + 64] = v.y;
        As[0][c4 * 4 + 2][row0 + 64] = v.z;
        As[0][c4 * 4 + 3][row0 + 64] = v.w;

        const float* pb = Bg + (size_t)cb0 * 1024 + colBase + hw4 * 4;
        *(float4*)&Bs[0][cb0][hw4 * 4]     = *(const float4*)pb;
        *(float4*)&Bs[0][cb0 + 8][hw4 * 4] = *(const float4*)(pb + 8 * 1024);
    }
    __syncthreads();

    int buf = 0;
    for (int kt = 0; kt < 48; ++kt) {
        float4 a0, a1, b0, b1;
        if (kt < 47) {
            const int kb = (kt + 1) * 16;
            const float* pa = Ag + (size_t)(rowBase + row0) * 768 + kb + c4 * 4;
            a0 = *(const float4*)pa;
            a1 = *(const float4*)(pa + 64 * 768);
            const float* pb = Bg + (size_t)(kb + cb0) * 1024 + colBase + hw4 * 4;
            b0 = *(const float4*)pb;
            b1 = *(const float4*)(pb + 8 * 1024);
        }

        #pragma unroll
        for (int kk = 0; kk < 16; ++kk) {
            float ar[8];
            *(float4*)&ar[0] = *(const float4*)&As[buf][kk][ty * 8];
            *(float4*)&ar[4] = *(const float4*)&As[buf][kk][ty * 8 + 4];
            // two 16B shared loads give the 8 b-values as 4 packed f32x2
            ulonglong2 bv0 = *(const ulonglong2*)&Bs[buf][kk][tx * 8];
            ulonglong2 bv1 = *(const ulonglong2*)&Bs[buf][kk][tx * 8 + 4];
            unsigned long long bb0 = bv0.x, bb1 = bv0.y, bb2 = bv1.x, bb3 = bv1.y;
            #pragma unroll
            for (int i = 0; i < 8; ++i) {
                unsigned long long a2 = bcast2(ar[i]);
                ffma2(acc2[i][0], a2, bb0);
                ffma2(acc2[i][1], a2, bb1);
                ffma2(acc2[i][2], a2, bb2);
                ffma2(acc2[i][3], a2, bb3);
            }
        }

        if (kt < 47) {
            const int nb = buf ^ 1;
            As[nb][c4 * 4 + 0][row0] = a0.x;
            As[nb][c4 * 4 + 1][row0] = a0.y;
            As[nb][c4 * 4 + 2][row0] = a0.z;
            As[nb][c4 * 4 + 3][row0] = a0.w;
            As[nb][c4 * 4 + 0][row0 + 64] = a1.x;
            As[nb][c4 * 4 + 1][row0 + 64] = a1.y;
            As[nb][c4 * 4 + 2][row0 + 64] = a1.z;
            As[nb][c4 * 4 + 3][row0 + 64] = a1.w;
            *(float4*)&Bs[nb][cb0][hw4 * 4]     = b0;
            *(float4*)&Bs[nb][cb0 + 8][hw4 * 4] = b1;
            __syncthreads();
            buf = nb;
        }
    }

    // ---- fused epilogue: sum of squared differences vs query ----
    if (t < 8) sdist[t] = 0.0f;
    __syncthreads();

    const float* Qb = Q + (size_t)b * 16 * 1024;
    float rs = 0.0f;
    #pragma unroll
    for (int i = 0; i < 8; ++i) {
        const int grow = rowBase + ty * 8 + i;
        const int qrow = grow & 15;
        const float* qp = Qb + (size_t)qrow * 1024 + colBase + tx * 8;
        #pragma unroll
        for (int jp = 0; jp < 4; ++jp) {
            float d0 = lo32(acc2[i][jp]) - qp[jp * 2];
            float d1 = hi32(acc2[i][jp]) - qp[jp * 2 + 1];
            rs += d0 * d0;
            rs += d1 * d1;
        }
    }
    atomicAdd(&sdist[ty >> 1], rs);
    __syncthreads();

    if (t < 8)
        atomicAdd(&g_dist2[b * 64 + blockIdx.y * 8 + t], sdist[t]);
}

// argmin over K=64 per batch, write codes (as float) and commit_loss.
__global__ void argmin_kernel(float* __restrict__ out)
{
    __shared__ float smin[32];
    const int b = threadIdx.x;   // 32 threads
    float best = 3.4e38f;
    int bi = 0;
    #pragma unroll 8
    for (int k = 0; k < 64; ++k) {
        float v = g_dist2[b * 64 + k];
        if (v < best) { best = v; bi = k; }
    }
    g_codes[b] = bi;
    out[524288 + b] = (float)bi;
    smin[b] = best;
    __syncthreads();
    if (b == 0) {
        float s = 0.0f;
        #pragma unroll
        for (int i = 0; i < 32; ++i) s += smin[i];
        out[524320] = s / 524288.0f;
    }
}

// Recompute sel[b] = W[codes[b]] @ F_b  (16 x 1024 per batch).
// grid = (32 col-tiles, 32 batches), 128 threads = 32 cols x 4 c-partitions.
__global__ __launch_bounds__(128)
void sel_kernel(const float* __restrict__ F,
                const float* __restrict__ W,
                float* __restrict__ out)
{
    const int b    = blockIdx.y;
    const int col  = blockIdx.x * 32 + (threadIdx.x & 31);
    const int part = threadIdx.x >> 5;       // 0..3, each owns 192 c's
    const int code = g_codes[b];

    const float* wp = W + (size_t)code * 16 * 768;
    const float* f  = F + (size_t)b * 768 * 1024 + col;

    float acc[16];
    #pragma unroll
    for (int q = 0; q < 16; ++q) acc[q] = 0.0f;

    const int c0 = part * 192;
    #pragma unroll 2
    for (int c = c0; c < c0 + 192; c += 2) {
        const float fv0 = __ldg(&f[(size_t)c * 1024]);
        const float fv1 = __ldg(&f[(size_t)(c + 1) * 1024]);
        #pragma unroll
        for (int q = 0; q < 16; ++q) {
            const float2 w2 = *(const float2*)&wp[q * 768 + c];  // warp-uniform
            acc[q] += w2.x * fv0;
            acc[q] += w2.y * fv1;
        }
    }

    __shared__ float red[4][16][32];
    const int lane = threadIdx.x & 31;
    #pragma unroll
    for (int q = 0; q < 16; ++q) red[part][q][lane] = acc[q];
    __syncthreads();

    if (part == 0) {
        float* op = out + (size_t)b * 16 * 1024 + col;
        #pragma unroll
        for (int q = 0; q < 16; ++q) {
            float s = red[0][q][lane] + red[1][q][lane]
                    + red[2][q][lane] + red[3][q][lane];
            op[(size_t)q * 1024] = s;
        }
    }
}

extern "C" void kernel_launch(void* const* d_in, const int* in_sizes, int n_in,
                              void* d_out, int out_size)
{
    const float* F = (const float*)d_in[0];   // features [32,768,32,32]
    const float* Q = (const float*)d_in[1];   // query    [32,16,32,32]
    const float* W = (const float*)d_in[2];   // W        [64,16,768]
    float* out = (float*)d_out;

    zero_dist_kernel<<<8, 256>>>();
    dist_gemm_kernel<<<dim3(8, 8, 32), 256>>>(F, Q, W);
    argmin_kernel<<<1, 32>>>(out);
    sel_kernel<<<dim3(32, 32), 128>>>(F, W, out);
}

// round 4
// speedup vs baseline: 2.5117x; 2.1579x over previous
#include <cuda_runtime.h>
#include <cuda_bf16.h>
#include <cstdint>

// features: [32, 768, 32, 32] -> F[b, c, hw], hw = 1024
// query:    [32, 16, 32, 32]  -> Q[b, q, hw]
// W:        [64, 16, 768]     -> A[r, c], r = k*16+q  (1024 x 768)
//
// dist2[b,k] = sum_{q,hw} (A@F_b - Q)^2 ; codes = argmin_k ; sel = recompute
// commit_loss recomputed EXACTLY from sel (fp32), so the GEMM only has to
// get the argmin right. GEMM: bf16 mma.sync with 3-term hi/lo split.

#define FN   (32 * 768 * 1024)
#define WN   (1024 * 768)

__device__ __nv_bfloat16 g_Fhi[FN];
__device__ __nv_bfloat16 g_Flo[FN];
__device__ __nv_bfloat16 g_Whi[WN];
__device__ __nv_bfloat16 g_Wlo[WN];
__device__ float g_dist2_part[32 * 512];   // [b][rowtile(8)][hwtile(8)][klocal(8)]
__device__ int   g_codes[32];
__device__ float g_loss_part[1024];

// ---------------- PTX helpers ----------------
__device__ __forceinline__ uint32_t smem_u32(const void* p) {
    uint32_t a;
    asm("{ .reg .u64 t; cvta.to.shared.u64 t, %1; cvt.u32.u64 %0, t; }" : "=r"(a) : "l"(p));
    return a;
}
__device__ __forceinline__ void cp16(uint32_t dst, const void* src) {
    asm volatile("cp.async.cg.shared.global [%0], [%1], 16;" :: "r"(dst), "l"(src));
}
#define CP_COMMIT() asm volatile("cp.async.commit_group;" ::: "memory")
#define CP_WAIT(n)  asm volatile("cp.async.wait_group %0;" :: "n"(n) : "memory")

__device__ __forceinline__ void ldsm_x4(uint32_t addr, uint32_t* r) {
    asm volatile("ldmatrix.sync.aligned.m8n8.x4.shared.b16 {%0,%1,%2,%3}, [%4];"
                 : "=r"(r[0]), "=r"(r[1]), "=r"(r[2]), "=r"(r[3]) : "r"(addr));
}
__device__ __forceinline__ void ldsm_x4_t(uint32_t addr, uint32_t* r) {
    asm volatile("ldmatrix.sync.aligned.m8n8.x4.trans.shared.b16 {%0,%1,%2,%3}, [%4];"
                 : "=r"(r[0]), "=r"(r[1]), "=r"(r[2]), "=r"(r[3]) : "r"(addr));
}
__device__ __forceinline__ void mma_bf16(float* c, const uint32_t* a, const uint32_t* b) {
    asm volatile(
        "mma.sync.aligned.m16n8k16.row.col.f32.bf16.bf16.f32 "
        "{%0,%1,%2,%3},{%4,%5,%6,%7},{%8,%9},{%0,%1,%2,%3};"
        : "+f"(c[0]), "+f"(c[1]), "+f"(c[2]), "+f"(c[3])
        : "r"(a[0]), "r"(a[1]), "r"(a[2]), "r"(a[3]), "r"(b[0]), "r"(b[1]));
}

// ---------------- fp32 -> bf16 hi/lo pre-conversion ----------------
__global__ void convF_kernel(const float* __restrict__ F) {
    const float4* src = (const float4*)F;
    __nv_bfloat162* hi2 = reinterpret_cast<__nv_bfloat162*>(g_Fhi);
    __nv_bfloat162* lo2 = reinterpret_cast<__nv_bfloat162*>(g_Flo);
    const int n4 = FN / 4;
    for (int i = blockIdx.x * blockDim.x + threadIdx.x; i < n4;
         i += gridDim.x * blockDim.x) {
        float4 v = src[i];
        __nv_bfloat16 hx = __float2bfloat16_rn(v.x);
        __nv_bfloat16 hy = __float2bfloat16_rn(v.y);
        __nv_bfloat16 hz = __float2bfloat16_rn(v.z);
        __nv_bfloat16 hw = __float2bfloat16_rn(v.w);
        __nv_bfloat16 lx = __float2bfloat16_rn(v.x - __bfloat162float(hx));
        __nv_bfloat16 ly = __float2bfloat16_rn(v.y - __bfloat162float(hy));
        __nv_bfloat16 lz = __float2bfloat16_rn(v.z - __bfloat162float(hz));
        __nv_bfloat16 lw = __float2bfloat16_rn(v.w - __bfloat162float(hw));
        hi2[i * 2 + 0] = __halves2bfloat162(hx, hy);
        hi2[i * 2 + 1] = __halves2bfloat162(hz, hw);
        lo2[i * 2 + 0] = __halves2bfloat162(lx, ly);
        lo2[i * 2 + 1] = __halves2bfloat162(lz, lw);
    }
}
__global__ void convW_kernel(const float* __restrict__ W) {
    const float4* src = (const float4*)W;
    __nv_bfloat162* hi2 = reinterpret_cast<__nv_bfloat162*>(g_Whi);
    __nv_bfloat162* lo2 = reinterpret_cast<__nv_bfloat162*>(g_Wlo);
    const int n4 = WN / 4;
    for (int i = blockIdx.x * blockDim.x + threadIdx.x; i < n4;
         i += gridDim.x * blockDim.x) {
        float4 v = src[i];
        __nv_bfloat16 hx = __float2bfloat16_rn(v.x);
        __nv_bfloat16 hy = __float2bfloat16_rn(v.y);
        __nv_bfloat16 hz = __float2bfloat16_rn(v.z);
        __nv_bfloat16 hw = __float2bfloat16_rn(v.w);
        __nv_bfloat16 lx = __float2bfloat16_rn(v.x - __bfloat162float(hx));
        __nv_bfloat16 ly = __float2bfloat16_rn(v.y - __bfloat162float(hy));
        __nv_bfloat16 lz = __float2bfloat16_rn(v.z - __bfloat162float(hz));
        __nv_bfloat16 lw = __float2bfloat16_rn(v.w - __bfloat162float(hw));
        hi2[i * 2 + 0] = __halves2bfloat162(hx, hy);
        hi2[i * 2 + 1] = __halves2bfloat162(hz, hw);
        lo2[i * 2 + 0] = __halves2bfloat162(lx, ly);
        lo2[i * 2 + 1] = __halves2bfloat162(lz, lw);
    }
}

// ---------------- dist GEMM: bf16 mma.sync, 3-pass split ----------------
// CTA tile 128x128, chunk K=32, double-buffered cp.async.
// smem stage layout (bytes): A_hi[128][80] @0, A_lo @10240,
//                            B_hi[32][272] @20480, B_lo @29184. stage=37888.
#define ST_ALO  10240
#define ST_BHI  20480
#define ST_BLO  29184
#define STAGE   37888
#define DSMEM   (2 * STAGE + 64)

__device__ __forceinline__ void load_stage(
    int t, int kb, uint32_t sbase, int rowBase, int colBase, size_t Foff)
{
    #pragma unroll
    for (int it = 0; it < 2; ++it) {
        int o = it * 256 + t;
        int row = o >> 2, seg = o & 3;
        const __nv_bfloat16* sh = g_Whi + (size_t)(rowBase + row) * 768 + kb + seg * 8;
        const __nv_bfloat16* sl = g_Wlo + (size_t)(rowBase + row) * 768 + kb + seg * 8;
        cp16(sbase + row * 80 + seg * 16, sh);
        cp16(sbase + ST_ALO + row * 80 + seg * 16, sl);
    }
    #pragma unroll
    for (int it = 0; it < 2; ++it) {
        int o = it * 256 + t;
        int row = o >> 4, seg = o & 15;
        const __nv_bfloat16* sh = g_Fhi + Foff + (size_t)(kb + row) * 1024 + colBase + seg * 8;
        const __nv_bfloat16* sl = g_Flo + Foff + (size_t)(kb + row) * 1024 + colBase + seg * 8;
        cp16(sbase + ST_BHI + row * 272 + seg * 16, sh);
        cp16(sbase + ST_BLO + row * 272 + seg * 16, sl);
    }
}

__global__ __launch_bounds__(256)
void dist_gemm_mma(const float* __restrict__ Q)
{
    extern __shared__ char smem[];
    const uint32_t sb = smem_u32(smem);
    float* sred = (float*)(smem + 2 * STAGE);   // [8][2]

    const int t    = threadIdx.x;
    const int wid  = t >> 5;
    const int lane = t & 31;
    const int wr   = wid & 3;      // warp row group (32 rows each)
    const int wc   = wid >> 2;     // warp col group (64 cols each)
    const int b       = blockIdx.z;
    const int rowBase = blockIdx.y * 128;
    const int colBase = blockIdx.x * 128;
    const size_t Foff = (size_t)b * 768 * 1024;

    // ldmatrix lane base addresses (within a stage)
    uint32_t a_addr[2];
    #pragma unroll
    for (int rt = 0; rt < 2; ++rt) {
        int row = wr * 32 + rt * 16 + (lane & 15);
        a_addr[rt] = sb + row * 80 + ((lane >> 4) * 16);
    }
    uint32_t b_addr[4];
    #pragma unroll
    for (int p = 0; p < 4; ++p) {
        int n = wc * 64 + p * 16 + (lane >> 4) * 8;
        b_addr[p] = sb + ST_BHI + (lane & 15) * 272 + n * 2;
    }

    float acc[2][8][4];
    #pragma unroll
    for (int i = 0; i < 2; ++i)
        #pragma unroll
        for (int j = 0; j < 8; ++j)
            #pragma unroll
            for (int v = 0; v < 4; ++v) acc[i][j][v] = 0.0f;

    // prologue: stages 0 and 1
    load_stage(t, 0, sb, rowBase, colBase, Foff);
    CP_COMMIT();
    load_stage(t, 32, sb + STAGE, rowBase, colBase, Foff);
    CP_COMMIT();

    for (int kt = 0; kt < 24; ++kt) {
        if (kt < 23) { CP_WAIT(1); } else { CP_WAIT(0); }
        __syncthreads();

        const uint32_t soff = (kt & 1) * STAGE;
        #pragma unroll
        for (int ks = 0; ks < 2; ++ks) {
            uint32_t ahi[2][4], alo[2][4], bh[16], bl[16];
            const uint32_t aoff = soff + ks * 32;
            const uint32_t boff = soff + ks * (16 * 272);
            #pragma unroll
            for (int rt = 0; rt < 2; ++rt) {
                ldsm_x4(a_addr[rt] + aoff, ahi[rt]);
                ldsm_x4(a_addr[rt] + aoff + ST_ALO, alo[rt]);
            }
            #pragma unroll
            for (int p = 0; p < 4; ++p) {
                ldsm_x4_t(b_addr[p] + boff, &bh[p * 4]);
                ldsm_x4_t(b_addr[p] + boff + (ST_BLO - ST_BHI), &bl[p * 4]);
            }
            #pragma unroll
            for (int rt = 0; rt < 2; ++rt)
                #pragma unroll
                for (int nt = 0; nt < 8; ++nt)
                    mma_bf16(acc[rt][nt], ahi[rt], &bh[nt * 2]);
            #pragma unroll
            for (int rt = 0; rt < 2; ++rt)
                #pragma unroll
                for (int nt = 0; nt < 8; ++nt)
                    mma_bf16(acc[rt][nt], ahi[rt], &bl[nt * 2]);
            #pragma unroll
            for (int rt = 0; rt < 2; ++rt)
                #pragma unroll
                for (int nt = 0; nt < 8; ++nt)
                    mma_bf16(acc[rt][nt], alo[rt], &bh[nt * 2]);
        }
        __syncthreads();

        if (kt + 2 < 24) {
            load_stage(t, (kt + 2) * 32, sb + soff, rowBase, colBase, Foff);
            CP_COMMIT();
        }
    }

    // ---- epilogue: (C - Q)^2, deterministic reduction per k-group ----
    // C frag: c0:(r=lane>>2, col=nt*8+(lane&3)*2) c1:col+1, c2/c3: r+8.
    // Q row depends only on (row & 15) -> same for both rt.
    const int qr0 = lane >> 2;
    const int cb  = colBase + wc * 64;
    float2 qa[8], qb[8];
    #pragma unroll
    for (int nt = 0; nt < 8; ++nt) {
        const float* q0 = Q + (size_t)b * 16384 + (size_t)qr0 * 1024 + cb + nt * 8 + (lane & 3) * 2;
        qa[nt] = *(const float2*)q0;
        qb[nt] = *(const float2*)(q0 + 8 * 1024);
    }
    #pragma unroll
    for (int rt = 0; rt < 2; ++rt) {
        float rs = 0.0f;
        #pragma unroll
        for (int nt = 0; nt < 8; ++nt) {
            float d0 = acc[rt][nt][0] - qa[nt].x;
            float d1 = acc[rt][nt][1] - qa[nt].y;
            float d2 = acc[rt][nt][2] - qb[nt].x;
            float d3 = acc[rt][nt][3] - qb[nt].y;
            rs += d0 * d0 + d1 * d1 + d2 * d2 + d3 * d3;
        }
        #pragma unroll
        for (int off = 16; off > 0; off >>= 1)
            rs += __shfl_xor_sync(0xffffffffu, rs, off);
        if (lane == 0) sred[wid * 2 + rt] = rs;
    }
    __syncthreads();
    if (t < 8) {
        // k_local = wr*2 + rt ; combine the two col-warps
        const int k = t;
        float s = sred[((k >> 1)) * 2 + (k & 1)] + sred[((k >> 1) + 4) * 2 + (k & 1)];
        g_dist2_part[b * 512 + blockIdx.y * 64 + blockIdx.x * 8 + k] = s;
    }
}

// ---------------- argmin (deterministic) ----------------
__global__ void argmin_kernel(float* __restrict__ out)
{
    const int b = threadIdx.x;   // 32 threads
    float best = 3.4e38f;
    int bi = 0;
    for (int k = 0; k < 64; ++k) {
        const float* p = g_dist2_part + b * 512 + (k >> 3) * 64 + (k & 7);
        float s = 0.0f;
        #pragma unroll
        for (int h = 0; h < 8; ++h) s += p[h * 8];
        if (s < best) { best = s; bi = k; }
    }
    g_codes[b] = bi;
    out[524288 + b] = (float)bi;
}

// ---------------- sel recompute (fp32 exact) + loss partials ----------------
// grid = (32 col-tiles, 32 batches), 128 threads = 32 cols x 4 c-partitions.
__global__ __launch_bounds__(128)
void sel_kernel(const float* __restrict__ F,
                const float* __restrict__ Q,
                const float* __restrict__ W,
                float* __restrict__ out)
{
    const int b    = blockIdx.y;
    const int col  = blockIdx.x * 32 + (threadIdx.x & 31);
    const int part = threadIdx.x >> 5;
    const int code = g_codes[b];

    const float* wp = W + (size_t)code * 16 * 768;
    const float* f  = F + (size_t)b * 768 * 1024 + col;

    float acc[16];
    #pragma unroll
    for (int q = 0; q < 16; ++q) acc[q] = 0.0f;

    const int c0 = part * 192;
    #pragma unroll 2
    for (int c = c0; c < c0 + 192; c += 4) {
        const float fv0 = __ldg(&f[(size_t)(c + 0) * 1024]);
        const float fv1 = __ldg(&f[(size_t)(c + 1) * 1024]);
        const float fv2 = __ldg(&f[(size_t)(c + 2) * 1024]);
        const float fv3 = __ldg(&f[(size_t)(c + 3) * 1024]);
        #pragma unroll
        for (int q = 0; q < 16; ++q) {
            const float4 w4 = *(const float4*)&wp[q * 768 + c];
            acc[q] += w4.x * fv0;
            acc[q] += w4.y * fv1;
            acc[q] += w4.z * fv2;
            acc[q] += w4.w * fv3;
        }
    }

    __shared__ float red[4][16][32];
    const int lane = threadIdx.x & 31;
    #pragma unroll
    for (int q = 0; q < 16; ++q) red[part][q][lane] = acc[q];
    __syncthreads();

    if (part == 0) {
        float* op = out + (size_t)b * 16 * 1024 + col;
        const float* qp = Q + (size_t)b * 16 * 1024 + col;
        float lsum = 0.0f;
        #pragma unroll
        for (int q = 0; q < 16; ++q) {
            float s = red[0][q][lane] + red[1][q][lane]
                    + red[2][q][lane] + red[3][q][lane];
            op[(size_t)q * 1024] = s;
            float d = s - qp[(size_t)q * 1024];
            lsum += d * d;
        }
        #pragma unroll
        for (int off = 16; off > 0; off >>= 1)
            lsum += __shfl_xor_sync(0xffffffffu, lsum, off);
        if (lane == 0)
            g_loss_part[b * 32 + blockIdx.x] = lsum;
    }
}

__global__ void loss_final(float* __restrict__ out)
{
    __shared__ float s[1024];
    const int t = threadIdx.x;
    s[t] = g_loss_part[t];
    __syncthreads();
    for (int o = 512; o > 0; o >>= 1) {
        if (t < o) s[t] += s[t + o];
        __syncthreads();
    }
    if (t == 0) out[524320] = s[0] / 524288.0f;
}

extern "C" void kernel_launch(void* const* d_in, const int* in_sizes, int n_in,
                              void* d_out, int out_size)
{
    const float* F = (const float*)d_in[0];
    const float* Q = (const float*)d_in[1];
    const float* W = (const float*)d_in[2];
    float* out = (float*)d_out;

    cudaFuncSetAttribute(dist_gemm_mma,
                         cudaFuncAttributeMaxDynamicSharedMemorySize, DSMEM);

    convF_kernel<<<4096, 256>>>(F);
    convW_kernel<<<768, 256>>>(W);
    dist_gemm_mma<<<dim3(8, 8, 32), 256, DSMEM>>>(Q);
    argmin_kernel<<<1, 32>>>(out);
    sel_kernel<<<dim3(32, 32), 128>>>(F, Q, W, out);
    loss_final<<<1, 1024>>>(out);
}

// round 6
// speedup vs baseline: 4.9529x; 1.9720x over previous
#include <cuda_runtime.h>
#include <cuda_fp16.h>
#include <cstdint>

// features: [32, 768, 32, 32] -> F[b, c, hw], hw = 1024
// query:    [32, 16, 32, 32]  -> Q[b, q, hw]
// W:        [64, 16, 768]     -> A[r, c], r = k*16+q  (1024 x 768)
//
// dist2[b,k] = sum_{q,hw} (A@F_b - Q)^2 ; codes = argmin_k ; sel = recompute.
// GEMM in pure fp16 mma.sync (dist2 err std ~0.14 << argmin gap ~150).
// sel + commit_loss recomputed EXACTLY in fp32, so output precision is fp32.

#define FN   (32 * 768 * 1024)
#define WN   (1024 * 768)

__device__ __half g_Fh[FN];
__device__ __half g_Wh[WN];
__device__ float g_dist2_part[32 * 512];   // [b][rowtile(8)][hwtile(8)][klocal(8)]
__device__ int   g_codes[32];
__device__ float g_loss_part[1024];

// ---------------- PTX helpers ----------------
__device__ __forceinline__ uint32_t smem_u32(const void* p) {
    uint32_t a;
    asm("{ .reg .u64 t; cvta.to.shared.u64 t, %1; cvt.u32.u64 %0, t; }" : "=r"(a) : "l"(p));
    return a;
}
__device__ __forceinline__ void cp16(uint32_t dst, const void* src) {
    asm volatile("cp.async.cg.shared.global [%0], [%1], 16;" :: "r"(dst), "l"(src));
}
#define CP_COMMIT() asm volatile("cp.async.commit_group;" ::: "memory")
#define CP_WAIT(n)  asm volatile("cp.async.wait_group %0;" :: "n"(n) : "memory")

__device__ __forceinline__ void ldsm_x4(uint32_t addr, uint32_t* r) {
    asm volatile("ldmatrix.sync.aligned.m8n8.x4.shared.b16 {%0,%1,%2,%3}, [%4];"
                 : "=r"(r[0]), "=r"(r[1]), "=r"(r[2]), "=r"(r[3]) : "r"(addr));
}
__device__ __forceinline__ void ldsm_x4_t(uint32_t addr, uint32_t* r) {
    asm volatile("ldmatrix.sync.aligned.m8n8.x4.trans.shared.b16 {%0,%1,%2,%3}, [%4];"
                 : "=r"(r[0]), "=r"(r[1]), "=r"(r[2]), "=r"(r[3]) : "r"(addr));
}
__device__ __forceinline__ void mma_f16(float* c, const uint32_t* a, const uint32_t* b) {
    asm volatile(
        "mma.sync.aligned.m16n8k16.row.col.f32.f16.f16.f32 "
        "{%0,%1,%2,%3},{%4,%5,%6,%7},{%8,%9},{%0,%1,%2,%3};"
        : "+f"(c[0]), "+f"(c[1]), "+f"(c[2]), "+f"(c[3])
        : "r"(a[0]), "r"(a[1]), "r"(a[2]), "r"(a[3]), "r"(b[0]), "r"(b[1]));
}

// ---------------- fp32 -> fp16 pre-conversion ----------------
__global__ void convF_kernel(const float* __restrict__ F) {
    const float4* src = (const float4*)F;
    __half2* h2 = reinterpret_cast<__half2*>(g_Fh);
    const int n4 = FN / 4;
    for (int i = blockIdx.x * blockDim.x + threadIdx.x; i < n4;
         i += gridDim.x * blockDim.x) {
        float4 v = src[i];
        h2[i * 2 + 0] = __floats2half2_rn(v.x, v.y);
        h2[i * 2 + 1] = __floats2half2_rn(v.z, v.w);
    }
}
__global__ void convW_kernel(const float* __restrict__ W) {
    const float4* src = (const float4*)W;
    __half2* h2 = reinterpret_cast<__half2*>(g_Wh);
    const int n4 = WN / 4;
    for (int i = blockIdx.x * blockDim.x + threadIdx.x; i < n4;
         i += gridDim.x * blockDim.x) {
        float4 v = src[i];
        h2[i * 2 + 0] = __floats2half2_rn(v.x, v.y);
        h2[i * 2 + 1] = __floats2half2_rn(v.z, v.w);
    }
}

// ---------------- dist GEMM: fp16 mma.sync, 1 pass ----------------
// CTA tile 128x128, chunk K=32, double-buffered cp.async.
// smem stage: A[128][80B] @0 (10240), B[32][272B] @10240 (8704). stage=18944.
#define ST_B    10240
#define STAGE   18944
#define DSMEM   (2 * STAGE + 64)

__device__ __forceinline__ void load_stage(
    int t, int kb, uint32_t sbase, int rowBase, int colBase, size_t Foff)
{
    // A: 128 rows x 32 fp16 = 64B/row = 4 x 16B chunks -> 512 cp16, 2/thread
    #pragma unroll
    for (int it = 0; it < 2; ++it) {
        int o = it * 256 + t;
        int row = o >> 2, seg = o & 3;
        const __half* s = g_Wh + (size_t)(rowBase + row) * 768 + kb + seg * 8;
        cp16(sbase + row * 80 + seg * 16, s);
    }
    // B: 32 rows x 128 fp16 = 256B/row = 16 x 16B chunks -> 512 cp16, 2/thread
    #pragma unroll
    for (int it = 0; it < 2; ++it) {
        int o = it * 256 + t;
        int row = o >> 4, seg = o & 15;
        const __half* s = g_Fh + Foff + (size_t)(kb + row) * 1024 + colBase + seg * 8;
        cp16(sbase + ST_B + row * 272 + seg * 16, s);
    }
}

__global__ __launch_bounds__(256)
void dist_gemm_mma(const float* __restrict__ Q)
{
    extern __shared__ char smem[];
    const uint32_t sb = smem_u32(smem);
    float* sred = (float*)(smem + 2 * STAGE);   // [8][2]

    const int t    = threadIdx.x;
    const int wid  = t >> 5;
    const int lane = t & 31;
    const int wr   = wid & 3;      // warp row group (32 rows)
    const int wc   = wid >> 2;     // warp col group (64 cols)
    const int b       = blockIdx.z;
    const int rowBase = blockIdx.y * 128;
    const int colBase = blockIdx.x * 128;
    const size_t Foff = (size_t)b * 768 * 1024;

    uint32_t a_addr[2];
    #pragma unroll
    for (int rt = 0; rt < 2; ++rt) {
        int row = wr * 32 + rt * 16 + (lane & 15);
        a_addr[rt] = sb + row * 80 + ((lane >> 4) * 16);
    }
    uint32_t b_addr[4];
    #pragma unroll
    for (int p = 0; p < 4; ++p) {
        int n = wc * 64 + p * 16 + (lane >> 4) * 8;
        b_addr[p] = sb + ST_B + (lane & 15) * 272 + n * 2;
    }

    float acc[2][8][4];
    #pragma unroll
    for (int i = 0; i < 2; ++i)
        #pragma unroll
        for (int j = 0; j < 8; ++j)
            #pragma unroll
            for (int v = 0; v < 4; ++v) acc[i][j][v] = 0.0f;

    load_stage(t, 0, sb, rowBase, colBase, Foff);
    CP_COMMIT();
    load_stage(t, 32, sb + STAGE, rowBase, colBase, Foff);
    CP_COMMIT();

    for (int kt = 0; kt < 24; ++kt) {
        if (kt < 23) { CP_WAIT(1); } else { CP_WAIT(0); }
        __syncthreads();

        const uint32_t soff = (kt & 1) * STAGE;
        #pragma unroll
        for (int ks = 0; ks < 2; ++ks) {
            uint32_t ah[2][4], bh[16];
            const uint32_t aoff = soff + ks * 32;
            const uint32_t boff = soff + ks * (16 * 272);
            #pragma unroll
            for (int rt = 0; rt < 2; ++rt)
                ldsm_x4(a_addr[rt] + aoff, ah[rt]);
            #pragma unroll
            for (int p = 0; p < 4; ++p)
                ldsm_x4_t(b_addr[p] + boff, &bh[p * 4]);
            #pragma unroll
            for (int rt = 0; rt < 2; ++rt)
                #pragma unroll
                for (int nt = 0; nt < 8; ++nt)
                    mma_f16(acc[rt][nt], ah[rt], &bh[nt * 2]);
        }
        __syncthreads();

        if (kt + 2 < 24) {
            load_stage(t, (kt + 2) * 32, sb + soff, rowBase, colBase, Foff);
            CP_COMMIT();
        }
    }

    // ---- epilogue: (C - Q)^2, deterministic reduction per k-group ----
    const int qr0 = lane >> 2;
    const int cb  = colBase + wc * 64;
    float2 qa[8], qb[8];
    #pragma unroll
    for (int nt = 0; nt < 8; ++nt) {
        const float* q0 = Q + (size_t)b * 16384 + (size_t)qr0 * 1024 + cb + nt * 8 + (lane & 3) * 2;
        qa[nt] = *(const float2*)q0;
        qb[nt] = *(const float2*)(q0 + 8 * 1024);
    }
    #pragma unroll
    for (int rt = 0; rt < 2; ++rt) {
        float rs = 0.0f;
        #pragma unroll
        for (int nt = 0; nt < 8; ++nt) {
            float d0 = acc[rt][nt][0] - qa[nt].x;
            float d1 = acc[rt][nt][1] - qa[nt].y;
            float d2 = acc[rt][nt][2] - qb[nt].x;
            float d3 = acc[rt][nt][3] - qb[nt].y;
            rs += d0 * d0 + d1 * d1 + d2 * d2 + d3 * d3;
        }
        #pragma unroll
        for (int off = 16; off > 0; off >>= 1)
            rs += __shfl_xor_sync(0xffffffffu, rs, off);
        if (lane == 0) sred[wid * 2 + rt] = rs;
    }
    __syncthreads();
    if (t < 8) {
        const int k = t;
        float s = sred[((k >> 1)) * 2 + (k & 1)] + sred[((k >> 1) + 4) * 2 + (k & 1)];
        g_dist2_part[b * 512 + blockIdx.y * 64 + blockIdx.x * 8 + k] = s;
    }
}

// ---------------- argmin: 1 block, warp-per-batch ----------------
__global__ __launch_bounds__(1024)
void argmin_kernel(float* __restrict__ out)
{
    const int b    = threadIdx.x >> 5;   // 32 warps = 32 batches
    const int lane = threadIdx.x & 31;

    float v[2];
    #pragma unroll
    for (int j = 0; j < 2; ++j) {
        const int k = lane * 2 + j;
        const float* p = g_dist2_part + b * 512 + (k >> 3) * 64 + (k & 7);
        float s0 = p[0]   + p[8]    + p[16]   + p[24];
        float s1 = p[32]  + p[40]   + p[48]   + p[56];
        v[j] = s0 + s1;
    }
    float best = v[0] < v[1] ? v[0] : v[1];
    int   bi   = v[0] < v[1] ? lane * 2 : lane * 2 + 1;
    #pragma unroll
    for (int off = 16; off > 0; off >>= 1) {
        float ov = __shfl_xor_sync(0xffffffffu, best, off);
        int   oi = __shfl_xor_sync(0xffffffffu, bi,   off);
        if (ov < best || (ov == best && oi < bi)) { best = ov; bi = oi; }
    }
    if (lane == 0) {
        g_codes[b] = bi;
        out[524288 + b] = (float)bi;
    }
}

// ---------------- sel recompute (fp32 exact) + loss partials ----------------
// grid = (32 col-tiles, 32 batches), 256 threads = 32 cols x 8 c-partitions.
__global__ __launch_bounds__(256)
void sel_kernel(const float* __restrict__ F,
                const float* __restrict__ Q,
                const float* __restrict__ W,
                float* __restrict__ out)
{
    const int b    = blockIdx.y;
    const int col  = blockIdx.x * 32 + (threadIdx.x & 31);
    const int part = threadIdx.x >> 5;       // 0..7, each owns 96 c's
    const int code = g_codes[b];

    const float* wp = W + (size_t)code * 16 * 768;
    const float* f  = F + (size_t)b * 768 * 1024 + col;

    float acc[16];
    #pragma unroll
    for (int q = 0; q < 16; ++q) acc[q] = 0.0f;

    const int c0 = part * 96;
    #pragma unroll 2
    for (int c = c0; c < c0 + 96; c += 4) {
        const float fv0 = __ldg(&f[(size_t)(c + 0) * 1024]);
        const float fv1 = __ldg(&f[(size_t)(c + 1) * 1024]);
        const float fv2 = __ldg(&f[(size_t)(c + 2) * 1024]);
        const float fv3 = __ldg(&f[(size_t)(c + 3) * 1024]);
        #pragma unroll
        for (int q = 0; q < 16; ++q) {
            const float4 w4 = *(const float4*)&wp[q * 768 + c];
            acc[q] += w4.x * fv0;
            acc[q] += w4.y * fv1;
            acc[q] += w4.z * fv2;
            acc[q] += w4.w * fv3;
        }
    }

    __shared__ float red[8][16][32];
    const int lane = threadIdx.x & 31;
    #pragma unroll
    for (int q = 0; q < 16; ++q) red[part][q][lane] = acc[q];
    __syncthreads();

    if (part == 0) {
        float* op = out + (size_t)b * 16 * 1024 + col;
        const float* qp = Q + (size_t)b * 16 * 1024 + col;
        float lsum = 0.0f;
        #pragma unroll
        for (int q = 0; q < 16; ++q) {
            float s = red[0][q][lane] + red[1][q][lane]
                    + red[2][q][lane] + red[3][q][lane]
                    + red[4][q][lane] + red[5][q][lane]
                    + red[6][q][lane] + red[7][q][lane];
            op[(size_t)q * 1024] = s;
            float d = s - qp[(size_t)q * 1024];
            lsum += d * d;
        }
        #pragma unroll
        for (int off = 16; off > 0; off >>= 1)
            lsum += __shfl_xor_sync(0xffffffffu, lsum, off);
        if (lane == 0)
            g_loss_part[b * 32 + blockIdx.x] = lsum;
    }
}

__global__ void loss_final(float* __restrict__ out)
{
    __shared__ float s[1024];
    const int t = threadIdx.x;
    s[t] = g_loss_part[t];
    __syncthreads();
    for (int o = 512; o > 0; o >>= 1) {
        if (t < o) s[t] += s[t + o];
        __syncthreads();
    }
    if (t == 0) out[524320] = s[0] / 524288.0f;
}

extern "C" void kernel_launch(void* const* d_in, const int* in_sizes, int n_in,
                              void* d_out, int out_size)
{
    const float* F = (const float*)d_in[0];
    const float* Q = (const float*)d_in[1];
    const float* W = (const float*)d_in[2];
    float* out = (float*)d_out;

    cudaFuncSetAttribute(dist_gemm_mma,
                         cudaFuncAttributeMaxDynamicSharedMemorySize, DSMEM);

    convF_kernel<<<2048, 256>>>(F);
    convW_kernel<<<768, 256>>>(W);
    dist_gemm_mma<<<dim3(8, 8, 32), 256, DSMEM>>>(Q);
    argmin_kernel<<<1, 1024>>>(out);
    sel_kernel<<<dim3(32, 32), 256>>>(F, Q, W, out);
    loss_final<<<1, 1024>>>(out);
}

// round 7
// speedup vs baseline: 5.1640x; 1.0426x over previous
#include <cuda_runtime.h>
#include <cuda_fp16.h>
#include <cstdint>

// features: [32, 768, 32, 32] -> F[b, c, hw], hw = 1024
// query:    [32, 16, 32, 32]  -> Q[b, q, hw]
// W:        [64, 16, 768]     -> A[r, c], r = k*16+q  (1024 x 768)
//
// dist2[b,k] = sum_{q,hw} (A@F_b - Q)^2 ; codes = argmin_k ; sel = recompute.
// GEMM in pure fp16 mma.sync (dist2 err std ~0.14 << argmin gap ~150).
// sel + commit_loss recomputed EXACTLY in fp32, so output precision is fp32.

#define FN   (32 * 768 * 1024)
#define WN   (1024 * 768)

__device__ __half g_Fh[FN];
__device__ __half g_Wh[WN];
__device__ float g_dist2_part[32 * 512];   // [b][rowtile(8)][hwtile(8)][klocal(8)]
__device__ int   g_codes[32];
__device__ float g_loss_part[1024];

// ---------------- PTX helpers ----------------
__device__ __forceinline__ uint32_t smem_u32(const void* p) {
    uint32_t a;
    asm("{ .reg .u64 t; cvta.to.shared.u64 t, %1; cvt.u32.u64 %0, t; }" : "=r"(a) : "l"(p));
    return a;
}
__device__ __forceinline__ void cp16(uint32_t dst, const void* src) {
    asm volatile("cp.async.cg.shared.global [%0], [%1], 16;" :: "r"(dst), "l"(src));
}
#define CP_COMMIT() asm volatile("cp.async.commit_group;" ::: "memory")
#define CP_WAIT(n)  asm volatile("cp.async.wait_group %0;" :: "n"(n) : "memory")

__device__ __forceinline__ void ldsm_x4(uint32_t addr, uint32_t* r) {
    asm volatile("ldmatrix.sync.aligned.m8n8.x4.shared.b16 {%0,%1,%2,%3}, [%4];"
                 : "=r"(r[0]), "=r"(r[1]), "=r"(r[2]), "=r"(r[3]) : "r"(addr));
}
__device__ __forceinline__ void ldsm_x4_t(uint32_t addr, uint32_t* r) {
    asm volatile("ldmatrix.sync.aligned.m8n8.x4.trans.shared.b16 {%0,%1,%2,%3}, [%4];"
                 : "=r"(r[0]), "=r"(r[1]), "=r"(r[2]), "=r"(r[3]) : "r"(addr));
}
__device__ __forceinline__ void mma_f16(float* c, const uint32_t* a, const uint32_t* b) {
    asm volatile(
        "mma.sync.aligned.m16n8k16.row.col.f32.f16.f16.f32 "
        "{%0,%1,%2,%3},{%4,%5,%6,%7},{%8,%9},{%0,%1,%2,%3};"
        : "+f"(c[0]), "+f"(c[1]), "+f"(c[2]), "+f"(c[3])
        : "r"(a[0]), "r"(a[1]), "r"(a[2]), "r"(a[3]), "r"(b[0]), "r"(b[1]));
}

// ---------------- fp32 -> fp16 pre-conversion ----------------
__global__ void convF_kernel(const float* __restrict__ F) {
    const float4* src = (const float4*)F;
    __half2* h2 = reinterpret_cast<__half2*>(g_Fh);
    const int n4 = FN / 4;
    for (int i = blockIdx.x * blockDim.x + threadIdx.x; i < n4;
         i += gridDim.x * blockDim.x) {
        float4 v = src[i];
        h2[i * 2 + 0] = __floats2half2_rn(v.x, v.y);
        h2[i * 2 + 1] = __floats2half2_rn(v.z, v.w);
    }
}
__global__ void convW_kernel(const float* __restrict__ W) {
    const float4* src = (const float4*)W;
    __half2* h2 = reinterpret_cast<__half2*>(g_Wh);
    const int n4 = WN / 4;
    for (int i = blockIdx.x * blockDim.x + threadIdx.x; i < n4;
         i += gridDim.x * blockDim.x) {
        float4 v = src[i];
        h2[i * 2 + 0] = __floats2half2_rn(v.x, v.y);
        h2[i * 2 + 1] = __floats2half2_rn(v.z, v.w);
    }
}

// ---------------- dist GEMM: fp16 mma.sync, 3-stage pipeline ----------------
// CTA tile 128x128, chunk K=32, 3-stage circular cp.async, 1 barrier/chunk.
// smem stage: A[128][80B] @0 (10240), B[32][272B] @10240 (8704). stage=18944.
#define ST_B    10240
#define STAGE   18944
#define NSTAGE  3
#define DSMEM   (NSTAGE * STAGE + 64)

__device__ __forceinline__ void load_stage(
    int t, int kb, uint32_t sbase, int rowBase, int colBase, size_t Foff)
{
    // A: 128 rows x 32 fp16 = 64B/row = 4 x 16B chunks -> 512 cp16, 2/thread
    #pragma unroll
    for (int it = 0; it < 2; ++it) {
        int o = it * 256 + t;
        int row = o >> 2, seg = o & 3;
        const __half* s = g_Wh + (size_t)(rowBase + row) * 768 + kb + seg * 8;
        cp16(sbase + row * 80 + seg * 16, s);
    }
    // B: 32 rows x 128 fp16 = 256B/row = 16 x 16B chunks -> 512 cp16, 2/thread
    #pragma unroll
    for (int it = 0; it < 2; ++it) {
        int o = it * 256 + t;
        int row = o >> 4, seg = o & 15;
        const __half* s = g_Fh + Foff + (size_t)(kb + row) * 1024 + colBase + seg * 8;
        cp16(sbase + ST_B + row * 272 + seg * 16, s);
    }
}

__global__ __launch_bounds__(256, 2)
void dist_gemm_mma(const float* __restrict__ Q)
{
    extern __shared__ char smem[];
    const uint32_t sb = smem_u32(smem);
    float* sred = (float*)(smem + NSTAGE * STAGE);   // [8][2]

    const int t    = threadIdx.x;
    const int wid  = t >> 5;
    const int lane = t & 31;
    const int wr   = wid & 3;      // warp row group (32 rows)
    const int wc   = wid >> 2;     // warp col group (64 cols)
    const int b       = blockIdx.z;
    const int rowBase = blockIdx.y * 128;
    const int colBase = blockIdx.x * 128;
    const size_t Foff = (size_t)b * 768 * 1024;

    uint32_t a_addr[2];
    #pragma unroll
    for (int rt = 0; rt < 2; ++rt) {
        int row = wr * 32 + rt * 16 + (lane & 15);
        a_addr[rt] = sb + row * 80 + ((lane >> 4) * 16);
    }
    uint32_t b_addr[4];
    #pragma unroll
    for (int p = 0; p < 4; ++p) {
        int n = wc * 64 + p * 16 + (lane >> 4) * 8;
        b_addr[p] = sb + ST_B + (lane & 15) * 272 + n * 2;
    }

    float acc[2][8][4];
    #pragma unroll
    for (int i = 0; i < 2; ++i)
        #pragma unroll
        for (int j = 0; j < 8; ++j)
            #pragma unroll
            for (int v = 0; v < 4; ++v) acc[i][j][v] = 0.0f;

    // prologue: chunks 0,1 into stages 0,1
    load_stage(t, 0, sb, rowBase, colBase, Foff);
    CP_COMMIT();
    load_stage(t, 32, sb + STAGE, rowBase, colBase, Foff);
    CP_COMMIT();

    int rd_stage = 0, wr_stage = 2;
    for (int kt = 0; kt < 24; ++kt) {
        CP_WAIT(1);          // chunk kt resident
        __syncthreads();     // all warps past chunk kt-1's compute

        // issue loads for chunk kt+2 into wr_stage (consumed at iter kt-1)
        if (kt + 2 < 24)
            load_stage(t, (kt + 2) * 32, sb + wr_stage * STAGE,
                       rowBase, colBase, Foff);
        CP_COMMIT();         // always commit (keeps group arithmetic exact)

        const uint32_t soff = rd_stage * STAGE;
        #pragma unroll
        for (int ks = 0; ks < 2; ++ks) {
            uint32_t ah[2][4], bh[16];
            const uint32_t aoff = soff + ks * 32;
            const uint32_t boff = soff + ks * (16 * 272);
            #pragma unroll
            for (int rt = 0; rt < 2; ++rt)
                ldsm_x4(a_addr[rt] + aoff, ah[rt]);
            #pragma unroll
            for (int p = 0; p < 4; ++p)
                ldsm_x4_t(b_addr[p] + boff, &bh[p * 4]);
            #pragma unroll
            for (int rt = 0; rt < 2; ++rt)
                #pragma unroll
                for (int nt = 0; nt < 8; ++nt)
                    mma_f16(acc[rt][nt], ah[rt], &bh[nt * 2]);
        }

        rd_stage = (rd_stage + 1) % NSTAGE;
        wr_stage = (wr_stage + 1) % NSTAGE;
    }

    // ---- epilogue: (C - Q)^2, deterministic reduction per k-group ----
    const int qr0 = lane >> 2;
    const int cb  = colBase + wc * 64;
    float2 qa[8], qb[8];
    #pragma unroll
    for (int nt = 0; nt < 8; ++nt) {
        const float* q0 = Q + (size_t)b * 16384 + (size_t)qr0 * 1024 + cb + nt * 8 + (lane & 3) * 2;
        qa[nt] = *(const float2*)q0;
        qb[nt] = *(const float2*)(q0 + 8 * 1024);
    }
    __syncthreads();   // ensure all reads of smem stages done before sred reuse
    #pragma unroll
    for (int rt = 0; rt < 2; ++rt) {
        float rs = 0.0f;
        #pragma unroll
        for (int nt = 0; nt < 8; ++nt) {
            float d0 = acc[rt][nt][0] - qa[nt].x;
            float d1 = acc[rt][nt][1] - qa[nt].y;
            float d2 = acc[rt][nt][2] - qb[nt].x;
            float d3 = acc[rt][nt][3] - qb[nt].y;
            rs += d0 * d0 + d1 * d1 + d2 * d2 + d3 * d3;
        }
        #pragma unroll
        for (int off = 16; off > 0; off >>= 1)
            rs += __shfl_xor_sync(0xffffffffu, rs, off);
        if (lane == 0) sred[wid * 2 + rt] = rs;
    }
    __syncthreads();
    if (t < 8) {
        const int k = t;
        float s = sred[((k >> 1)) * 2 + (k & 1)] + sred[((k >> 1) + 4) * 2 + (k & 1)];
        g_dist2_part[b * 512 + blockIdx.y * 64 + blockIdx.x * 8 + k] = s;
    }
}

// ---------------- argmin: 1 block, warp-per-batch ----------------
__global__ __launch_bounds__(1024)
void argmin_kernel(float* __restrict__ out)
{
    const int b    = threadIdx.x >> 5;   // 32 warps = 32 batches
    const int lane = threadIdx.x & 31;

    float v[2];
    #pragma unroll
    for (int j = 0; j < 2; ++j) {
        const int k = lane * 2 + j;
        const float* p = g_dist2_part + b * 512 + (k >> 3) * 64 + (k & 7);
        float s0 = p[0]   + p[8]    + p[16]   + p[24];
        float s1 = p[32]  + p[40]   + p[48]   + p[56];
        v[j] = s0 + s1;
    }
    float best = v[0] < v[1] ? v[0] : v[1];
    int   bi   = v[0] < v[1] ? lane * 2 : lane * 2 + 1;
    #pragma unroll
    for (int off = 16; off > 0; off >>= 1) {
        float ov = __shfl_xor_sync(0xffffffffu, best, off);
        int   oi = __shfl_xor_sync(0xffffffffu, bi,   off);
        if (ov < best || (ov == best && oi < bi)) { best = ov; bi = oi; }
    }
    if (lane == 0) {
        g_codes[b] = bi;
        out[524288 + b] = (float)bi;
    }
}

// ---------------- sel recompute (fp32 exact) + loss partials ----------------
// grid = (32 col-tiles, 32 batches), 256 threads = 32 cols x 8 c-partitions.
__global__ __launch_bounds__(256)
void sel_kernel(const float* __restrict__ F,
                const float* __restrict__ Q,
                const float* __restrict__ W,
                float* __restrict__ out)
{
    const int b    = blockIdx.y;
    const int col  = blockIdx.x * 32 + (threadIdx.x & 31);
    const int part = threadIdx.x >> 5;       // 0..7, each owns 96 c's
    const int code = g_codes[b];

    const float* wp = W + (size_t)code * 16 * 768;
    const float* f  = F + (size_t)b * 768 * 1024 + col;

    float acc[16];
    #pragma unroll
    for (int q = 0; q < 16; ++q) acc[q] = 0.0f;

    const int c0 = part * 96;
    #pragma unroll 2
    for (int c = c0; c < c0 + 96; c += 4) {
        const float fv0 = __ldg(&f[(size_t)(c + 0) * 1024]);
        const float fv1 = __ldg(&f[(size_t)(c + 1) * 1024]);
        const float fv2 = __ldg(&f[(size_t)(c + 2) * 1024]);
        const float fv3 = __ldg(&f[(size_t)(c + 3) * 1024]);
        #pragma unroll
        for (int q = 0; q < 16; ++q) {
            const float4 w4 = *(const float4*)&wp[q * 768 + c];
            acc[q] += w4.x * fv0;
            acc[q] += w4.y * fv1;
            acc[q] += w4.z * fv2;
            acc[q] += w4.w * fv3;
        }
    }

    __shared__ float red[8][16][32];
    const int lane = threadIdx.x & 31;
    #pragma unroll
    for (int q = 0; q < 16; ++q) red[part][q][lane] = acc[q];
    __syncthreads();

    if (part == 0) {
        float* op = out + (size_t)b * 16 * 1024 + col;
        const float* qp = Q + (size_t)b * 16 * 1024 + col;
        float lsum = 0.0f;
        #pragma unroll
        for (int q = 0; q < 16; ++q) {
            float s = red[0][q][lane] + red[1][q][lane]
                    + red[2][q][lane] + red[3][q][lane]
                    + red[4][q][lane] + red[5][q][lane]
                    + red[6][q][lane] + red[7][q][lane];
            op[(size_t)q * 1024] = s;
            float d = s - qp[(size_t)q * 1024];
            lsum += d * d;
        }
        #pragma unroll
        for (int off = 16; off > 0; off >>= 1)
            lsum += __shfl_xor_sync(0xffffffffu, lsum, off);
        if (lane == 0)
            g_loss_part[b * 32 + blockIdx.x] = lsum;
    }
}

__global__ void loss_final(float* __restrict__ out)
{
    __shared__ float s[1024];
    const int t = threadIdx.x;
    s[t] = g_loss_part[t];
    __syncthreads();
    for (int o = 512; o > 0; o >>= 1) {
        if (t < o) s[t] += s[t + o];
        __syncthreads();
    }
    if (t == 0) out[524320] = s[0] / 524288.0f;
}

extern "C" void kernel_launch(void* const* d_in, const int* in_sizes, int n_in,
                              void* d_out, int out_size)
{
    const float* F = (const float*)d_in[0];
    const float* Q = (const float*)d_in[1];
    const float* W = (const float*)d_in[2];
    float* out = (float*)d_out;

    cudaFuncSetAttribute(dist_gemm_mma,
                         cudaFuncAttributeMaxDynamicSharedMemorySize, DSMEM);

    convF_kernel<<<2048, 256>>>(F);
    convW_kernel<<<768, 256>>>(W);
    dist_gemm_mma<<<dim3(8, 8, 32), 256, DSMEM>>>(Q);
    argmin_kernel<<<1, 1024>>>(out);
    sel_kernel<<<dim3(32, 32), 256>>>(F, Q, W, out);
    loss_final<<<1, 1024>>>(out);
}

// round 8
// speedup vs baseline: 5.6528x; 1.0947x over previous
#include <cuda_runtime.h>
#include <cuda_fp16.h>
#include <cstdint>

// features: [32, 768, 32, 32] -> F[b, c, hw], hw = 1024
// query:    [32, 16, 32, 32]  -> Q[b, q, hw]
// W:        [64, 16, 768]     -> A[r, c], r = k*16+q  (1024 x 768)
//
// dist2[b,k] = sum_{q,hw} (A@F_b - Q)^2 ; codes = argmin_k ; sel = recompute.
// GEMM in pure fp16 mma.sync (dist2 err std ~0.14 << argmin gap ~150).
// sel + commit_loss recomputed EXACTLY in fp32, so output precision is fp32.

#define FN   (32 * 768 * 1024)
#define WN   (1024 * 768)

__device__ __half g_Fh[FN];
__device__ __half g_Wh[WN];
__device__ float g_dist2_part[32 * 512];   // [b][rowtile(8)][hwtile(8)][klocal(8)]
__device__ int   g_codes[32];
__device__ float g_loss_part[1024];

// ---------------- PTX helpers ----------------
__device__ __forceinline__ uint32_t smem_u32(const void* p) {
    uint32_t a;
    asm("{ .reg .u64 t; cvta.to.shared.u64 t, %1; cvt.u32.u64 %0, t; }" : "=r"(a) : "l"(p));
    return a;
}
__device__ __forceinline__ void cp16(uint32_t dst, const void* src) {
    asm volatile("cp.async.cg.shared.global [%0], [%1], 16;" :: "r"(dst), "l"(src));
}
#define CP_COMMIT() asm volatile("cp.async.commit_group;" ::: "memory")
#define CP_WAIT(n)  asm volatile("cp.async.wait_group %0;" :: "n"(n) : "memory")

__device__ __forceinline__ void ldsm_x4(uint32_t addr, uint32_t* r) {
    asm volatile("ldmatrix.sync.aligned.m8n8.x4.shared.b16 {%0,%1,%2,%3}, [%4];"
                 : "=r"(r[0]), "=r"(r[1]), "=r"(r[2]), "=r"(r[3]) : "r"(addr));
}
__device__ __forceinline__ void ldsm_x4_t(uint32_t addr, uint32_t* r) {
    asm volatile("ldmatrix.sync.aligned.m8n8.x4.trans.shared.b16 {%0,%1,%2,%3}, [%4];"
                 : "=r"(r[0]), "=r"(r[1]), "=r"(r[2]), "=r"(r[3]) : "r"(addr));
}
__device__ __forceinline__ void mma_f16(float* c, const uint32_t* a, const uint32_t* b) {
    asm volatile(
        "mma.sync.aligned.m16n8k16.row.col.f32.f16.f16.f32 "
        "{%0,%1,%2,%3},{%4,%5,%6,%7},{%8,%9},{%0,%1,%2,%3};"
        : "+f"(c[0]), "+f"(c[1]), "+f"(c[2]), "+f"(c[3])
        : "r"(a[0]), "r"(a[1]), "r"(a[2]), "r"(a[3]), "r"(b[0]), "r"(b[1]));
}

// ---------------- fp32 -> fp16 pre-conversion ----------------
__global__ void convF_kernel(const float* __restrict__ F) {
    const float4* src = (const float4*)F;
    __half2* h2 = reinterpret_cast<__half2*>(g_Fh);
    const int n4 = FN / 4;
    for (int i = blockIdx.x * blockDim.x + threadIdx.x; i < n4;
         i += gridDim.x * blockDim.x) {
        float4 v = src[i];
        h2[i * 2 + 0] = __floats2half2_rn(v.x, v.y);
        h2[i * 2 + 1] = __floats2half2_rn(v.z, v.w);
    }
}
__global__ void convW_kernel(const float* __restrict__ W) {
    const float4* src = (const float4*)W;
    __half2* h2 = reinterpret_cast<__half2*>(g_Wh);
    const int n4 = WN / 4;
    for (int i = blockIdx.x * blockDim.x + threadIdx.x; i < n4;
         i += gridDim.x * blockDim.x) {
        float4 v = src[i];
        h2[i * 2 + 0] = __floats2half2_rn(v.x, v.y);
        h2[i * 2 + 1] = __floats2half2_rn(v.z, v.w);
    }
}

// ---------------- dist GEMM: fp16 mma.sync ----------------
// CTA tile 128x128, 4 warps (warp tile 64x64), chunk K=32,
// 5-stage cp.async ring with load-issue ahead of wait+barrier.
// smem stage: A[128][80B] @0 (10240), B[32][272B] @10240 (8704). stage=18944.
#define ST_B    10240
#define STAGE   18944
#define NSTAGE  5
#define DSMEM   (NSTAGE * STAGE + 64)

__device__ __forceinline__ void load_stage(
    int t, int kb, uint32_t sbase, int rowBase, int colBase, size_t Foff)
{
    // A: 128 rows x 32 fp16 = 64B/row = 4 x 16B chunks -> 512 cp16, 4/thread
    #pragma unroll
    for (int it = 0; it < 4; ++it) {
        int o = it * 128 + t;
        int row = o >> 2, seg = o & 3;
        const __half* s = g_Wh + (size_t)(rowBase + row) * 768 + kb + seg * 8;
        cp16(sbase + row * 80 + seg * 16, s);
    }
    // B: 32 rows x 128 fp16 = 256B/row = 16 x 16B chunks -> 512 cp16, 4/thread
    #pragma unroll
    for (int it = 0; it < 4; ++it) {
        int o = it * 128 + t;
        int row = o >> 4, seg = o & 15;
        const __half* s = g_Fh + Foff + (size_t)(kb + row) * 1024 + colBase + seg * 8;
        cp16(sbase + ST_B + row * 272 + seg * 16, s);
    }
}

__global__ __launch_bounds__(128, 2)
void dist_gemm_mma(const float* __restrict__ Q)
{
    extern __shared__ char smem[];
    const uint32_t sb = smem_u32(smem);
    float* sred = (float*)(smem + NSTAGE * STAGE);   // [8 k][2 colgrp]

    const int t    = threadIdx.x;
    const int wid  = t >> 5;        // 0..3
    const int lane = t & 31;
    const int wr   = wid & 1;       // warp row group (64 rows)
    const int wc   = wid >> 1;      // warp col group (64 cols)
    const int b       = blockIdx.z;
    const int rowBase = blockIdx.y * 128;
    const int colBase = blockIdx.x * 128;
    const size_t Foff = (size_t)b * 768 * 1024;

    uint32_t a_addr[4];
    #pragma unroll
    for (int rt = 0; rt < 4; ++rt) {
        int row = wr * 64 + rt * 16 + (lane & 15);
        a_addr[rt] = sb + row * 80 + ((lane >> 4) * 16);
    }
    uint32_t b_addr[4];
    #pragma unroll
    for (int p = 0; p < 4; ++p) {
        int n = wc * 64 + p * 16 + (lane >> 4) * 8;
        b_addr[p] = sb + ST_B + (lane & 15) * 272 + n * 2;
    }

    float acc[4][8][4];
    #pragma unroll
    for (int i = 0; i < 4; ++i)
        #pragma unroll
        for (int j = 0; j < 8; ++j)
            #pragma unroll
            for (int v = 0; v < 4; ++v) acc[i][j][v] = 0.0f;

    // prologue: chunks 0..2 into stages 0..2
    load_stage(t, 0, sb, rowBase, colBase, Foff);
    CP_COMMIT();
    load_stage(t, 32, sb + STAGE, rowBase, colBase, Foff);
    CP_COMMIT();
    load_stage(t, 64, sb + 2 * STAGE, rowBase, colBase, Foff);
    CP_COMMIT();

    for (int kt = 0; kt < 24; ++kt) {
        // issue chunk kt+3 into stage (kt+3)%5 BEFORE waiting.
        // That stage was consumed at iter kt-2, fenced by iter kt-1's barrier.
        if (kt + 3 < 24)
            load_stage(t, (kt + 3) * 32, sb + ((kt + 3) % NSTAGE) * STAGE,
                       rowBase, colBase, Foff);
        CP_COMMIT();          // always commit (keeps group arithmetic exact)
        CP_WAIT(3);           // chunk kt resident
        __syncthreads();      // all warps past chunk kt-1's compute

        const uint32_t soff = (kt % NSTAGE) * STAGE;
        #pragma unroll
        for (int ks = 0; ks < 2; ++ks) {
            uint32_t ah[4][4], bh[16];
            const uint32_t aoff = soff + ks * 32;
            const uint32_t boff = soff + ks * (16 * 272);
            #pragma unroll
            for (int rt = 0; rt < 4; ++rt)
                ldsm_x4(a_addr[rt] + aoff, ah[rt]);
            #pragma unroll
            for (int p = 0; p < 4; ++p)
                ldsm_x4_t(b_addr[p] + boff, &bh[p * 4]);
            #pragma unroll
            for (int rt = 0; rt < 4; ++rt)
                #pragma unroll
                for (int nt = 0; nt < 8; ++nt)
                    mma_f16(acc[rt][nt], ah[rt], &bh[nt * 2]);
        }
    }

    // ---- epilogue: (C - Q)^2, deterministic reduction per k-group ----
    // Each rt tile (16 rows) is exactly one k group: k_local = wr*4 + rt.
    const int qr0 = lane >> 2;
    const int cb  = colBase + wc * 64;
    float2 qa[8], qb[8];
    #pragma unroll
    for (int nt = 0; nt < 8; ++nt) {
        const float* q0 = Q + (size_t)b * 16384 + (size_t)qr0 * 1024 + cb + nt * 8 + (lane & 3) * 2;
        qa[nt] = *(const float2*)q0;
        qb[nt] = *(const float2*)(q0 + 8 * 1024);
    }
    __syncthreads();   // stages idle; sred region safe
    #pragma unroll
    for (int rt = 0; rt < 4; ++rt) {
        float rs = 0.0f;
        #pragma unroll
        for (int nt = 0; nt < 8; ++nt) {
            float d0 = acc[rt][nt][0] - qa[nt].x;
            float d1 = acc[rt][nt][1] - qa[nt].y;
            float d2 = acc[rt][nt][2] - qb[nt].x;
            float d3 = acc[rt][nt][3] - qb[nt].y;
            rs += d0 * d0 + d1 * d1 + d2 * d2 + d3 * d3;
        }
        #pragma unroll
        for (int off = 16; off > 0; off >>= 1)
            rs += __shfl_xor_sync(0xffffffffu, rs, off);
        if (lane == 0) sred[(wr * 4 + rt) * 2 + wc] = rs;
    }
    __syncthreads();
    if (t < 8) {
        float s = sred[t * 2 + 0] + sred[t * 2 + 1];
        g_dist2_part[b * 512 + blockIdx.y * 64 + blockIdx.x * 8 + t] = s;
    }
}

// ---------------- argmin: 1 block, warp-per-batch ----------------
__global__ __launch_bounds__(1024)
void argmin_kernel(float* __restrict__ out)
{
    const int b    = threadIdx.x >> 5;   // 32 warps = 32 batches
    const int lane = threadIdx.x & 31;

    float v[2];
    #pragma unroll
    for (int j = 0; j < 2; ++j) {
        const int k = lane * 2 + j;
        const float* p = g_dist2_part + b * 512 + (k >> 3) * 64 + (k & 7);
        float s0 = p[0]   + p[8]    + p[16]   + p[24];
        float s1 = p[32]  + p[40]   + p[48]   + p[56];
        v[j] = s0 + s1;
    }
    float best = v[0] < v[1] ? v[0] : v[1];
    int   bi   = v[0] < v[1] ? lane * 2 : lane * 2 + 1;
    #pragma unroll
    for (int off = 16; off > 0; off >>= 1) {
        float ov = __shfl_xor_sync(0xffffffffu, best, off);
        int   oi = __shfl_xor_sync(0xffffffffu, bi,   off);
        if (ov < best || (ov == best && oi < bi)) { best = ov; bi = oi; }
    }
    if (lane == 0) {
        g_codes[b] = bi;
        out[524288 + b] = (float)bi;
    }
}

// ---------------- sel recompute (fp32 exact) + loss partials ----------------
// grid = (32 col-tiles, 32 batches), 256 threads = 32 cols x 8 c-partitions.
__global__ __launch_bounds__(256)
void sel_kernel(const float* __restrict__ F,
                const float* __restrict__ Q,
                const float* __restrict__ W,
                float* __restrict__ out)
{
    const int b    = blockIdx.y;
    const int col  = blockIdx.x * 32 + (threadIdx.x & 31);
    const int part = threadIdx.x >> 5;       // 0..7, each owns 96 c's
    const int code = g_codes[b];

    const float* wp = W + (size_t)code * 16 * 768;
    const float* f  = F + (size_t)b * 768 * 1024 + col;

    float acc[16];
    #pragma unroll
    for (int q = 0; q < 16; ++q) acc[q] = 0.0f;

    const int c0 = part * 96;
    #pragma unroll 2
    for (int c = c0; c < c0 + 96; c += 4) {
        const float fv0 = __ldg(&f[(size_t)(c + 0) * 1024]);
        const float fv1 = __ldg(&f[(size_t)(c + 1) * 1024]);
        const float fv2 = __ldg(&f[(size_t)(c + 2) * 1024]);
        const float fv3 = __ldg(&f[(size_t)(c + 3) * 1024]);
        #pragma unroll
        for (int q = 0; q < 16; ++q) {
            const float4 w4 = *(const float4*)&wp[q * 768 + c];
            acc[q] += w4.x * fv0;
            acc[q] += w4.y * fv1;
            acc[q] += w4.z * fv2;
            acc[q] += w4.w * fv3;
        }
    }

    __shared__ float red[8][16][32];
    const int lane = threadIdx.x & 31;
    #pragma unroll
    for (int q = 0; q < 16; ++q) red[part][q][lane] = acc[q];
    __syncthreads();

    if (part == 0) {
        float* op = out + (size_t)b * 16 * 1024 + col;
        const float* qp = Q + (size_t)b * 16 * 1024 + col;
        float lsum = 0.0f;
        #pragma unroll
        for (int q = 0; q < 16; ++q) {
            float s = red[0][q][lane] + red[1][q][lane]
                    + red[2][q][lane] + red[3][q][lane]
                    + red[4][q][lane] + red[5][q][lane]
                    + red[6][q][lane] + red[7][q][lane];
            op[(size_t)q * 1024] = s;
            float d = s - qp[(size_t)q * 1024];
            lsum += d * d;
        }
        #pragma unroll
        for (int off = 16; off > 0; off >>= 1)
            lsum += __shfl_xor_sync(0xffffffffu, lsum, off);
        if (lane == 0)
            g_loss_part[b * 32 + blockIdx.x] = lsum;
    }
}

__global__ void loss_final(float* __restrict__ out)
{
    __shared__ float s[1024];
    const int t = threadIdx.x;
    s[t] = g_loss_part[t];
    __syncthreads();
    for (int o = 512; o > 0; o >>= 1) {
        if (t < o) s[t] += s[t + o];
        __syncthreads();
    }
    if (t == 0) out[524320] = s[0] / 524288.0f;
}

extern "C" void kernel_launch(void* const* d_in, const int* in_sizes, int n_in,
                              void* d_out, int out_size)
{
    const float* F = (const float*)d_in[0];
    const float* Q = (const float*)d_in[1];
    const float* W = (const float*)d_in[2];
    float* out = (float*)d_out;

    cudaFuncSetAttribute(dist_gemm_mma,
                         cudaFuncAttributeMaxDynamicSharedMemorySize, DSMEM);

    convF_kernel<<<2048, 256>>>(F);
    convW_kernel<<<768, 256>>>(W);
    dist_gemm_mma<<<dim3(8, 8, 32), 128, DSMEM>>>(Q);
    argmin_kernel<<<1, 1024>>>(out);
    sel_kernel<<<dim3(32, 32), 256>>>(F, Q, W, out);
    loss_final<<<1, 1024>>>(out);
}